// round 13
// baseline (speedup 1.0000x reference)
#include <cuda_runtime.h>
#include <math.h>

// Problem constants
#define B_    4
#define HQ_   32
#define HKV_  8
#define D_    128
#define SPAST 8192
#define KVLEN 8193
#define HID   4096
#define NTOT  6144
#define TOKB  256
#define INITB 4
#define RECB  256
#define NKEEP (INITB + TOKB + RECB)   // 516
#define NCAND 7933                    // positions [4, 7936]
#define SSTRIDE 8208
#define SCALE 0.08838834764831845f
#define NSPLIT 64

// ------------- scratch -------------
__device__ float g_qkv   [4 * NTOT];
__device__ float g_q     [B_ * HQ_ * D_];
__device__ float g_knew  [B_ * HKV_ * D_];
__device__ float g_vnew  [B_ * HKV_ * D_];
__device__ float g_scores[B_ * HQ_ * SSTRIDE];
__device__ float g_attn  [B_ * HQ_ * D_];

// ------------- helpers -------------
__device__ __forceinline__ float warpsum(float v) {
    #pragma unroll
    for (int o = 16; o > 0; o >>= 1) v += __shfl_xor_sync(0xFFFFFFFFu, v, o);
    return v;
}
__device__ __forceinline__ float warpmax(float v) {
    #pragma unroll
    for (int o = 16; o > 0; o >>= 1) v = fmaxf(v, __shfl_xor_sync(0xFFFFFFFFu, v, o));
    return v;
}
__device__ __forceinline__ float dot4(float4 a, float4 b) {
    return a.x * b.x + a.y * b.y + a.z * b.z + a.w * b.w;
}
__device__ __forceinline__ float fold(float lo, float hi, int o, int lane) {
    float mine  = (lane & o) ? hi : lo;
    float other = (lane & o) ? lo : hi;
    return mine + __shfl_xor_sync(0xFFFFFFFFu, other, o);
}
__device__ __forceinline__ unsigned xform(unsigned u) {
    return (u & 0x80000000u) ? ~u : (u | 0x80000000u);
}

// ------------- Kernel 1: QKV GEMV (split-K=64, 4-way intra-block k-split, FULL unroll) -------------
// grid (12, NSPLIT), block 512. Four 128-thread quarters split the 64-K chunk;
// partials combined in smem; quarter 0 issues the atomics (same atomic count as before).
__global__ __launch_bounds__(512)
void qkv_gemv(const float* __restrict__ h, const float* __restrict__ wq,
              const float* __restrict__ wk, const float* __restrict__ wv) {
    __shared__ float sh[256];       // [4 batches][64 k]
    __shared__ float comb[3 * 2048];// quarters 1-3 partials: [128 threads][16 floats]
    int tid = threadIdx.x;
    int t = tid & 127, quad = tid >> 7;   // 0..3
    int k0 = blockIdx.y * 64;
    if (tid < 256) {
        int b = tid >> 6, k = tid & 63;
        sh[tid] = h[b * HID + k0 + k];
    }
    __syncthreads();
    int c0 = blockIdx.x * 512;
    const float* w; int stride, col;
    if (c0 < 4096)      { w = wq; stride = 4096; col = c0; }
    else if (c0 < 5120) { w = wk; stride = 1024; col = c0 - 4096; }
    else                { w = wv; stride = 1024; col = c0 - 5120; }
    const float* wp = w + (size_t)(k0 + quad * 16) * stride + col + t * 4;
    const float* shh = sh + quad * 16;
    float4 a0 = make_float4(0,0,0,0), a1 = a0, a2 = a0, a3 = a0;
    #pragma unroll
    for (int k = 0; k < 16; k++) {
        float4 wv4 = *(const float4*)(wp + (size_t)k * stride);
        float h0 = shh[k], h1 = shh[64 + k], h2 = shh[128 + k], h3 = shh[192 + k];
        a0.x = fmaf(h0, wv4.x, a0.x); a0.y = fmaf(h0, wv4.y, a0.y);
        a0.z = fmaf(h0, wv4.z, a0.z); a0.w = fmaf(h0, wv4.w, a0.w);
        a1.x = fmaf(h1, wv4.x, a1.x); a1.y = fmaf(h1, wv4.y, a1.y);
        a1.z = fmaf(h1, wv4.z, a1.z); a1.w = fmaf(h1, wv4.w, a1.w);
        a2.x = fmaf(h2, wv4.x, a2.x); a2.y = fmaf(h2, wv4.y, a2.y);
        a2.z = fmaf(h2, wv4.z, a2.z); a2.w = fmaf(h2, wv4.w, a2.w);
        a3.x = fmaf(h3, wv4.x, a3.x); a3.y = fmaf(h3, wv4.y, a3.y);
        a3.z = fmaf(h3, wv4.z, a3.z); a3.w = fmaf(h3, wv4.w, a3.w);
    }
    if (quad != 0) {
        float4* cb = (float4*)(comb + (quad - 1) * 2048 + t * 16);
        cb[0] = a0; cb[1] = a1; cb[2] = a2; cb[3] = a3;
    }
    __syncthreads();
    if (quad == 0) {
        #pragma unroll
        for (int q = 0; q < 3; q++) {
            const float4* cb = (const float4*)(comb + q * 2048 + t * 16);
            float4 b0 = cb[0], b1 = cb[1], b2 = cb[2], b3 = cb[3];
            a0.x += b0.x; a0.y += b0.y; a0.z += b0.z; a0.w += b0.w;
            a1.x += b1.x; a1.y += b1.y; a1.z += b1.z; a1.w += b1.w;
            a2.x += b2.x; a2.y += b2.y; a2.z += b2.z; a2.w += b2.w;
            a3.x += b3.x; a3.y += b3.y; a3.z += b3.z; a3.w += b3.w;
        }
        int c = c0 + t * 4;
        atomicAdd(&g_qkv[c],     a0.x); atomicAdd(&g_qkv[c + 1],     a0.y);
        atomicAdd(&g_qkv[c + 2], a0.z); atomicAdd(&g_qkv[c + 3],     a0.w);
        atomicAdd(&g_qkv[NTOT + c],     a1.x); atomicAdd(&g_qkv[NTOT + c + 1], a1.y);
        atomicAdd(&g_qkv[NTOT + c + 2], a1.z); atomicAdd(&g_qkv[NTOT + c + 3], a1.w);
        atomicAdd(&g_qkv[2*NTOT + c],     a2.x); atomicAdd(&g_qkv[2*NTOT + c + 1], a2.y);
        atomicAdd(&g_qkv[2*NTOT + c + 2], a2.z); atomicAdd(&g_qkv[2*NTOT + c + 3], a2.w);
        atomicAdd(&g_qkv[3*NTOT + c],     a3.x); atomicAdd(&g_qkv[3*NTOT + c + 1], a3.y);
        atomicAdd(&g_qkv[3*NTOT + c + 2], a3.z); atomicAdd(&g_qkv[3*NTOT + c + 3], a3.w);
    }
}

// ------------- Kernel 2: RoPE + accumulator reset -------------
__global__ void qkv_reduce(const float* __restrict__ cosp, const float* __restrict__ sinp) {
    int idx = blockIdx.x * blockDim.x + threadIdx.x;
    if (idx >= 4 * 3584) return;
    int b = idx / 3584, r = idx % 3584;
    float* gq = g_qkv + b * NTOT;
    if (r < 2560) {
        int head = r >> 6, d = r & 63;
        int col1 = head * 128 + d, col2 = col1 + 64;
        float s1 = gq[col1], s2 = gq[col2];
        gq[col1] = 0.f; gq[col2] = 0.f;
        float c1 = cosp[b * D_ + d],      sn1 = sinp[b * D_ + d];
        float c2 = cosp[b * D_ + d + 64], sn2 = sinp[b * D_ + d + 64];
        float r1 = s1 * c1 - s2 * sn1;
        float r2 = s2 * c2 + s1 * sn2;
        if (head < 32) {
            g_q[(b * HQ_ + head) * D_ + d]      = r1;
            g_q[(b * HQ_ + head) * D_ + d + 64] = r2;
        } else {
            int kh = head - 32;
            g_knew[(b * HKV_ + kh) * D_ + d]      = r1;
            g_knew[(b * HKV_ + kh) * D_ + d + 64] = r2;
        }
    } else {
        int lc = r - 2560;
        float s = gq[5120 + lc];
        gq[5120 + lc] = 0.f;
        g_vnew[b * HKV_ * D_ + lc] = s;
    }
}

// ------------- Kernel 3: scores -------------
__global__ void scores_kernel(const float* __restrict__ pk) {
    int bh = blockIdx.y;
    int b = bh >> 3, hkv = bh & 7;
    int tid = threadIdx.x, warp = tid >> 5, lane = tid & 31;
    __shared__ float qsh[512];
    const float* qsrc = g_q + (size_t)(b * HQ_ + hkv * 4) * D_;
    for (int i = tid; i < 512; i += 256) qsh[i] = qsrc[i];
    __syncthreads();
    float4 q0 = *(const float4*)(qsh +   0 + lane * 4);
    float4 q1 = *(const float4*)(qsh + 128 + lane * 4);
    float4 q2 = *(const float4*)(qsh + 256 + lane * 4);
    float4 q3 = *(const float4*)(qsh + 384 + lane * 4);
    int base = blockIdx.x * 256;
    float* srow = g_scores + (size_t)(b * HQ_ + hkv * 4) * SSTRIDE;
    const float* kbase = pk + ((size_t)bh << 20);
    const float* knrow = g_knew + bh * D_;
    int rr = ((lane >> 4) & 1) * 2 + ((lane >> 3) & 1);
    int hh = ((lane >> 2) & 1) * 2 + ((lane >> 1) & 1);
    int p0 = base + warp * 32;
    bool fast = (p0 + 31 < SPAST);
    if (fast) {
        #pragma unroll 2
        for (int j = 0; j < 32; j += 4) {
            int p = p0 + j;
            const float* rp = kbase + ((size_t)p << 7) + lane * 4;
            float4 k0v = *(const float4*)(rp);
            float4 k1v = *(const float4*)(rp + 128);
            float4 k2v = *(const float4*)(rp + 256);
            float4 k3v = *(const float4*)(rp + 384);
            float d00 = dot4(k0v, q0), d01 = dot4(k0v, q1), d02 = dot4(k0v, q2), d03 = dot4(k0v, q3);
            float d10 = dot4(k1v, q0), d11 = dot4(k1v, q1), d12 = dot4(k1v, q2), d13 = dot4(k1v, q3);
            float d20 = dot4(k2v, q0), d21 = dot4(k2v, q1), d22 = dot4(k2v, q2), d23 = dot4(k2v, q3);
            float d30 = dot4(k3v, q0), d31 = dot4(k3v, q1), d32 = dot4(k3v, q2), d33 = dot4(k3v, q3);
            float t00 = fold(d00, d20, 16, lane), t01 = fold(d01, d21, 16, lane);
            float t02 = fold(d02, d22, 16, lane), t03 = fold(d03, d23, 16, lane);
            float t10 = fold(d10, d30, 16, lane), t11 = fold(d11, d31, 16, lane);
            float t12 = fold(d12, d32, 16, lane), t13 = fold(d13, d33, 16, lane);
            float u0 = fold(t00, t10, 8, lane), u1 = fold(t01, t11, 8, lane);
            float u2 = fold(t02, t12, 8, lane), u3 = fold(t03, t13, 8, lane);
            float w0 = fold(u0, u2, 4, lane), w1 = fold(u1, u3, 4, lane);
            float x = fold(w0, w1, 2, lane);
            x += __shfl_xor_sync(0xFFFFFFFFu, x, 1);
            if ((lane & 1) == 0)
                srow[hh * SSTRIDE + p + rr] = x * SCALE;
        }
    } else {
        for (int j = 0; j < 32; j += 4) {
            int p = p0 + j;
            if (p >= KVLEN) break;
            const float* r0p = (p     < SPAST) ? kbase + ((size_t) p      << 7) : knrow;
            const float* r1p = (p + 1 < SPAST) ? kbase + ((size_t)(p + 1) << 7) : knrow;
            const float* r2p = (p + 2 < SPAST) ? kbase + ((size_t)(p + 2) << 7) : knrow;
            const float* r3p = (p + 3 < SPAST) ? kbase + ((size_t)(p + 3) << 7) : knrow;
            float4 k0v = *(const float4*)(r0p + lane * 4);
            float4 k1v = *(const float4*)(r1p + lane * 4);
            float4 k2v = *(const float4*)(r2p + lane * 4);
            float4 k3v = *(const float4*)(r3p + lane * 4);
            float d00 = dot4(k0v, q0), d01 = dot4(k0v, q1), d02 = dot4(k0v, q2), d03 = dot4(k0v, q3);
            float d10 = dot4(k1v, q0), d11 = dot4(k1v, q1), d12 = dot4(k1v, q2), d13 = dot4(k1v, q3);
            float d20 = dot4(k2v, q0), d21 = dot4(k2v, q1), d22 = dot4(k2v, q2), d23 = dot4(k2v, q3);
            float d30 = dot4(k3v, q0), d31 = dot4(k3v, q1), d32 = dot4(k3v, q2), d33 = dot4(k3v, q3);
            float t00 = fold(d00, d20, 16, lane), t01 = fold(d01, d21, 16, lane);
            float t02 = fold(d02, d22, 16, lane), t03 = fold(d03, d23, 16, lane);
            float t10 = fold(d10, d30, 16, lane), t11 = fold(d11, d31, 16, lane);
            float t12 = fold(d12, d32, 16, lane), t13 = fold(d13, d33, 16, lane);
            float u0 = fold(t00, t10, 8, lane), u1 = fold(t01, t11, 8, lane);
            float u2 = fold(t02, t12, 8, lane), u3 = fold(t03, t13, 8, lane);
            float w0 = fold(u0, u2, 4, lane), w1 = fold(u1, u3, 4, lane);
            float x = fold(w0, w1, 2, lane);
            x += __shfl_xor_sync(0xFFFFFFFFu, x, 1);
            if ((lane & 1) == 0 && p + rr < KVLEN)
                srow[hh * SSTRIDE + p + rr] = x * SCALE;
        }
    }
}

// ------------- Kernel 4: FUSED select (3-level radix, register keys) + softmax + V gather -------------
// (R11 version — fastest measured: 15.1us; DO NOT warp-specialize, measured slower twice)
#define KPT 8
template<int NB>
__device__ __forceinline__ void scan_pick_desc(const int* hist, int* warpsums,
                                               int* sh_bin, int* sh_kk, int tid) {
    int kk = *sh_kk;
    int nb = 1024 * NB;
    int b0 = nb - 1 - tid * NB;
    int c[NB]; int s = 0;
    #pragma unroll
    for (int q = 0; q < NB; q++) { c[q] = hist[b0 - q]; s += c[q]; }
    int v = s; int lane = tid & 31;
    #pragma unroll
    for (int o = 1; o < 32; o <<= 1) {
        int n = __shfl_up_sync(0xFFFFFFFFu, v, o);
        if (lane >= o) v += n;
    }
    if (lane == 31) warpsums[tid >> 5] = v;
    __syncthreads();
    if (tid == 0) {
        int a = 0;
        #pragma unroll
        for (int w = 0; w < 32; w++) { int t = warpsums[w]; warpsums[w] = a; a += t; }
    }
    __syncthreads();
    int excl = v - s + warpsums[tid >> 5];
    if (excl < kk && excl + s >= kk) {
        int acc = excl;
        #pragma unroll
        for (int q = 0; q < NB; q++) {
            if (acc < kk && acc + c[q] >= kk) { *sh_bin = b0 - q; *sh_kk = kk - acc; break; }
            acc += c[q];
        }
    }
    __syncthreads();
}
__device__ __forceinline__ void scan_pick_256(const int* hist, int* warpsums,
                                              int* sh_bin, int* sh_kk, int tid) {
    int kk = *sh_kk;
    int v = 0, s = 0;
    if (tid < 256) {
        s = hist[255 - tid];
        v = s;
        int lane = tid & 31;
        #pragma unroll
        for (int o = 1; o < 32; o <<= 1) {
            int n = __shfl_up_sync(0xFFFFFFFFu, v, o);
            if (lane >= o) v += n;
        }
        if (lane == 31) warpsums[tid >> 5] = v;
    }
    __syncthreads();
    if (tid == 0) {
        int a = 0;
        #pragma unroll
        for (int w = 0; w < 8; w++) { int t = warpsums[w]; warpsums[w] = a; a += t; }
    }
    __syncthreads();
    if (tid < 256) {
        v += warpsums[tid >> 5];
        int prev = v - s;
        if (v >= kk && prev < kk) { *sh_bin = 255 - tid; *sh_kk = kk - prev; }
    }
    __syncthreads();
}

__global__ __launch_bounds__(1024, 1)
void select_attnv_kernel(const float* __restrict__ pv, float* __restrict__ out) {
    __shared__ __align__(16) char s_buf[32768];
    __shared__ int warpsums[32];
    __shared__ int sh_bin, sh_kk, sh_wpos, sh_eq;
    __shared__ int selsh[TOKB];
    __shared__ float sc[NKEEP];
    __shared__ int   idxsh[NKEEP];
    __shared__ float red[32];
    __shared__ float M_sh, Z_sh;
    int* hist = (int*)s_buf;
    float* outsh = (float*)s_buf;

    int bh = blockIdx.x, tid = threadIdx.x;
    int b = bh >> 5, hq = bh & 31, hkv = hq >> 2;
    int warp = tid >> 5, lane = tid & 31;
    if (tid < 128) out[bh * 128 + tid] = 0.f;
    const float* srow = g_scores + (size_t)bh * SSTRIDE;

    hist[tid] = 0; hist[tid + 1024] = 0;
    if (tid == 0) { sh_kk = TOKB; sh_wpos = 0; sh_eq = 0; }
    __syncthreads();
    unsigned key[KPT];
    int ibase = tid * KPT;
    if (ibase + KPT - 1 < NCAND) {
        float4 f0 = *(const float4*)(srow + INITB + ibase);
        float4 f1 = *(const float4*)(srow + INITB + ibase + 4);
        key[0] = xform(__float_as_uint(f0.x)); key[1] = xform(__float_as_uint(f0.y));
        key[2] = xform(__float_as_uint(f0.z)); key[3] = xform(__float_as_uint(f0.w));
        key[4] = xform(__float_as_uint(f1.x)); key[5] = xform(__float_as_uint(f1.y));
        key[6] = xform(__float_as_uint(f1.z)); key[7] = xform(__float_as_uint(f1.w));
        #pragma unroll
        for (int j = 0; j < KPT; j++) atomicAdd(&hist[key[j] >> 21], 1);
    } else {
        #pragma unroll
        for (int j = 0; j < KPT; j++) {
            int i = ibase + j;
            unsigned u = 0;
            if (i < NCAND) {
                u = xform(__float_as_uint(srow[INITB + i]));
                atomicAdd(&hist[u >> 21], 1);
            }
            key[j] = u;
        }
    }
    __syncthreads();
    scan_pick_desc<2>(hist, warpsums, &sh_bin, &sh_kk, tid);
    unsigned B1 = (unsigned)sh_bin;
    #pragma unroll
    for (int q = 0; q < 8; q++) hist[tid + q * 1024] = 0;
    __syncthreads();
    #pragma unroll
    for (int j = 0; j < KPT; j++) {
        int i = ibase + j;
        if (i < NCAND) {
            unsigned t = key[j] >> 21;
            if (t > B1) selsh[atomicAdd(&sh_wpos, 1)] = INITB + i;
            else if (t == B1) atomicAdd(&hist[(key[j] >> 8) & 0x1FFF], 1);
        }
    }
    __syncthreads();
    scan_pick_desc<8>(hist, warpsums, &sh_bin, &sh_kk, tid);
    unsigned B2 = (unsigned)sh_bin;
    unsigned P24 = (B1 << 13) | B2;
    if (tid < 256) hist[tid] = 0;
    __syncthreads();
    #pragma unroll
    for (int j = 0; j < KPT; j++) {
        int i = ibase + j;
        if (i < NCAND && (key[j] >> 21) == B1) {
            unsigned t = (key[j] >> 8) & 0x1FFF;
            if (t > B2) selsh[atomicAdd(&sh_wpos, 1)] = INITB + i;
            else if (t == B2) atomicAdd(&hist[key[j] & 255], 1);
        }
    }
    __syncthreads();
    scan_pick_256(hist, warpsums, &sh_bin, &sh_kk, tid);
    unsigned tau = (P24 << 8) | (unsigned)sh_bin;
    int needeq = sh_kk;
    #pragma unroll
    for (int j = 0; j < KPT; j++) {
        int i = ibase + j;
        if (i < NCAND && (key[j] >> 8) == P24) {
            if (key[j] > tau) selsh[atomicAdd(&sh_wpos, 1)] = INITB + i;
            else if (key[j] == tau) {
                if (atomicAdd(&sh_eq, 1) < needeq)
                    selsh[atomicAdd(&sh_wpos, 1)] = INITB + i;
            }
        }
    }
    __syncthreads();

    // ---- attnv phase ----
    if (tid < NKEEP) {
        int i = tid, p;
        if (i < INITB) p = i;
        else if (i < INITB + TOKB) p = selsh[i - INITB];
        else p = (KVLEN - RECB) + (i - INITB - TOKB);
        idxsh[i] = p;
        sc[i] = srow[p];
    }
    __syncthreads();
    float m = (tid < NKEEP) ? sc[tid] : -INFINITY;
    m = warpmax(m);
    if (lane == 0) red[warp] = m;
    __syncthreads();
    if (tid == 0) {
        float mm = red[0];
        #pragma unroll
        for (int w = 1; w < 32; w++) mm = fmaxf(mm, red[w]);
        M_sh = mm;
    }
    __syncthreads();
    float M = M_sh;
    float z = 0.f;
    if (tid < NKEEP) {
        float e = __expf(sc[tid] - M);
        sc[tid] = e;
        z = e;
    }
    z = warpsum(z);
    if (lane == 0) red[warp] = z;
    __syncthreads();
    if (tid == 0) {
        float zz = 0.f;
        #pragma unroll
        for (int w = 0; w < 32; w++) zz += red[w];
        Z_sh = zz;
    }
    __syncthreads();
    float inv = 1.0f / Z_sh;
    float4 acc = make_float4(0.f, 0.f, 0.f, 0.f);
    const float* vbase = pv + ((size_t)(b * HKV_ + hkv) << 20);
    const float* vnrow = g_vnew + (b * HKV_ + hkv) * D_;
    for (int i = warp; i < NKEEP; i += 128) {
        float ww[4];
        const float* vp[4];
        #pragma unroll
        for (int u = 0; u < 4; u++) {
            int ii = i + u * 32;
            bool vld = ii < NKEEP;
            int p = vld ? idxsh[ii] : 0;
            ww[u] = vld ? sc[ii] * inv : 0.f;
            vp[u] = (p < SPAST) ? (vbase + ((size_t)p << 7)) : vnrow;
        }
        float4 v0 = *(const float4*)(vp[0] + lane * 4);
        float4 v1 = *(const float4*)(vp[1] + lane * 4);
        float4 v2 = *(const float4*)(vp[2] + lane * 4);
        float4 v3 = *(const float4*)(vp[3] + lane * 4);
        acc.x = fmaf(ww[0], v0.x, acc.x); acc.y = fmaf(ww[0], v0.y, acc.y);
        acc.z = fmaf(ww[0], v0.z, acc.z); acc.w = fmaf(ww[0], v0.w, acc.w);
        acc.x = fmaf(ww[1], v1.x, acc.x); acc.y = fmaf(ww[1], v1.y, acc.y);
        acc.z = fmaf(ww[1], v1.z, acc.z); acc.w = fmaf(ww[1], v1.w, acc.w);
        acc.x = fmaf(ww[2], v2.x, acc.x); acc.y = fmaf(ww[2], v2.y, acc.y);
        acc.z = fmaf(ww[2], v2.z, acc.z); acc.w = fmaf(ww[2], v2.w, acc.w);
        acc.x = fmaf(ww[3], v3.x, acc.x); acc.y = fmaf(ww[3], v3.y, acc.y);
        acc.z = fmaf(ww[3], v3.z, acc.z); acc.w = fmaf(ww[3], v3.w, acc.w);
    }
    float* os = outsh + warp * 128 + lane * 4;
    os[0] = acc.x; os[1] = acc.y; os[2] = acc.z; os[3] = acc.w;
    __syncthreads();
    if (tid < 128) {
        float s = 0.f;
        #pragma unroll
        for (int w = 0; w < 32; w++) s += outsh[w * 128 + tid];
        g_attn[bh * D_ + tid] = s;
    }
}

// ------------- Kernel 5: output projection GEMV (4-way intra-block k-split, FULL unroll) -------------
// grid (8, NSPLIT), block 512.
__global__ __launch_bounds__(512)
void out_gemv(const float* __restrict__ wo, float* __restrict__ out) {
    __shared__ float sh[256];
    __shared__ float comb[3 * 2048];
    int tid = threadIdx.x;
    int t = tid & 127, quad = tid >> 7;
    int k0 = blockIdx.y * 64;
    if (tid < 256) {
        int b = tid >> 6, k = tid & 63;
        sh[tid] = g_attn[b * HID + k0 + k];
    }
    __syncthreads();
    int col = blockIdx.x * 512 + t * 4;
    const float* wp = wo + (size_t)(k0 + quad * 16) * HID + col;
    const float* shh = sh + quad * 16;
    float4 a0 = make_float4(0,0,0,0), a1 = a0, a2 = a0, a3 = a0;
    #pragma unroll
    for (int k = 0; k < 16; k++) {
        float4 wv4 = *(const float4*)(wp + (size_t)k * HID);
        float h0 = shh[k], h1 = shh[64 + k], h2 = shh[128 + k], h3 = shh[192 + k];
        a0.x = fmaf(h0, wv4.x, a0.x); a0.y = fmaf(h0, wv4.y, a0.y);
        a0.z = fmaf(h0, wv4.z, a0.z); a0.w = fmaf(h0, wv4.w, a0.w);
        a1.x = fmaf(h1, wv4.x, a1.x); a1.y = fmaf(h1, wv4.y, a1.y);
        a1.z = fmaf(h1, wv4.z, a1.z); a1.w = fmaf(h1, wv4.w, a1.w);
        a2.x = fmaf(h2, wv4.x, a2.x); a2.y = fmaf(h2, wv4.y, a2.y);
        a2.z = fmaf(h2, wv4.z, a2.z); a2.w = fmaf(h2, wv4.w, a2.w);
        a3.x = fmaf(h3, wv4.x, a3.x); a3.y = fmaf(h3, wv4.y, a3.y);
        a3.z = fmaf(h3, wv4.z, a3.z); a3.w = fmaf(h3, wv4.w, a3.w);
    }
    if (quad != 0) {
        float4* cb = (float4*)(comb + (quad - 1) * 2048 + t * 16);
        cb[0] = a0; cb[1] = a1; cb[2] = a2; cb[3] = a3;
    }
    __syncthreads();
    if (quad == 0) {
        #pragma unroll
        for (int q = 0; q < 3; q++) {
            const float4* cb = (const float4*)(comb + q * 2048 + t * 16);
            float4 b0 = cb[0], b1 = cb[1], b2 = cb[2], b3 = cb[3];
            a0.x += b0.x; a0.y += b0.y; a0.z += b0.z; a0.w += b0.w;
            a1.x += b1.x; a1.y += b1.y; a1.z += b1.z; a1.w += b1.w;
            a2.x += b2.x; a2.y += b2.y; a2.z += b2.z; a2.w += b2.w;
            a3.x += b3.x; a3.y += b3.y; a3.z += b3.z; a3.w += b3.w;
        }
        atomicAdd(&out[col],     a0.x); atomicAdd(&out[col + 1],     a0.y);
        atomicAdd(&out[col + 2], a0.z); atomicAdd(&out[col + 3],     a0.w);
        atomicAdd(&out[HID + col],     a1.x); atomicAdd(&out[HID + col + 1], a1.y);
        atomicAdd(&out[HID + col + 2], a1.z); atomicAdd(&out[HID + col + 3], a1.w);
        atomicAdd(&out[2*HID + col],     a2.x); atomicAdd(&out[2*HID + col + 1], a2.y);
        atomicAdd(&out[2*HID + col + 2], a2.z); atomicAdd(&out[2*HID + col + 3], a2.w);
        atomicAdd(&out[3*HID + col],     a3.x); atomicAdd(&out[3*HID + col + 1], a3.y);
        atomicAdd(&out[3*HID + col + 2], a3.z); atomicAdd(&out[3*HID + col + 3], a3.w);
    }
}

// ------------- launch -------------
extern "C" void kernel_launch(void* const* d_in, const int* in_sizes, int n_in,
                              void* d_out, int out_size) {
    const float* h    = (const float*)d_in[0];
    const float* cosp = (const float*)d_in[1];
    const float* sinp = (const float*)d_in[2];
    const float* pk   = (const float*)d_in[3];
    const float* pv   = (const float*)d_in[4];
    const float* wq   = (const float*)d_in[5];
    const float* wk   = (const float*)d_in[6];
    const float* wv   = (const float*)d_in[7];
    const float* wo   = (const float*)d_in[8];
    float* out = (float*)d_out;

    qkv_gemv<<<dim3(12, NSPLIT), 512>>>(h, wq, wk, wv);
    qkv_reduce<<<(4 * 3584 + 255) / 256, 256>>>(cosp, sinp);
    scores_kernel<<<dim3(33, 32), 256>>>(pk);
    select_attnv_kernel<<<128, 1024>>>(pv, out);
    out_gemv<<<dim3(8, NSPLIT), 512>>>(wo, out);
}

// round 14
// speedup vs baseline: 1.0269x; 1.0269x over previous
#include <cuda_runtime.h>
#include <math.h>

// Problem constants
#define B_    4
#define HQ_   32
#define HKV_  8
#define D_    128
#define SPAST 8192
#define KVLEN 8193
#define HID   4096
#define NTOT  6144
#define TOKB  256
#define INITB 4
#define RECB  256
#define NKEEP (INITB + TOKB + RECB)   // 516
#define NCAND 7933                    // positions [4, 7936]
#define SSTRIDE 8208
#define SCALE 0.08838834764831845f
#define NSPLIT 64

// ------------- scratch -------------
__device__ float g_qkv   [4 * NTOT];
__device__ float g_q     [B_ * HQ_ * D_];
__device__ float g_knew  [B_ * HKV_ * D_];
__device__ float g_vnew  [B_ * HKV_ * D_];
__device__ float g_scores[B_ * HQ_ * SSTRIDE];
__device__ float g_attn  [B_ * HQ_ * D_];

// ------------- helpers -------------
__device__ __forceinline__ float warpsum(float v) {
    #pragma unroll
    for (int o = 16; o > 0; o >>= 1) v += __shfl_xor_sync(0xFFFFFFFFu, v, o);
    return v;
}
__device__ __forceinline__ float warpmax(float v) {
    #pragma unroll
    for (int o = 16; o > 0; o >>= 1) v = fmaxf(v, __shfl_xor_sync(0xFFFFFFFFu, v, o));
    return v;
}
__device__ __forceinline__ float dot4(float4 a, float4 b) {
    return a.x * b.x + a.y * b.y + a.z * b.z + a.w * b.w;
}
__device__ __forceinline__ float fold(float lo, float hi, int o, int lane) {
    float mine  = (lane & o) ? hi : lo;
    float other = (lane & o) ? lo : hi;
    return mine + __shfl_xor_sync(0xFFFFFFFFu, other, o);
}
__device__ __forceinline__ unsigned xform(unsigned u) {
    return (u & 0x80000000u) ? ~u : (u | 0x80000000u);
}

// ------------- Kernel 1: QKV GEMV (split-K=64, 2-way intra-block k-split, FULL unroll) -------------
__global__ __launch_bounds__(256)
void qkv_gemv(const float* __restrict__ h, const float* __restrict__ wq,
              const float* __restrict__ wk, const float* __restrict__ wv) {
    __shared__ float sh[256];
    __shared__ float comb[2048];
    int tid = threadIdx.x;
    int t = tid & 127, half = tid >> 7;
    int k0 = blockIdx.y * 64;
    {
        int b = tid >> 6, k = tid & 63;
        sh[tid] = h[b * HID + k0 + k];
    }
    __syncthreads();
    int c0 = blockIdx.x * 512;
    const float* w; int stride, col;
    if (c0 < 4096)      { w = wq; stride = 4096; col = c0; }
    else if (c0 < 5120) { w = wk; stride = 1024; col = c0 - 4096; }
    else                { w = wv; stride = 1024; col = c0 - 5120; }
    const float* wp = w + (size_t)(k0 + half * 32) * stride + col + t * 4;
    const float* shh = sh + half * 32;
    float4 a0 = make_float4(0,0,0,0), a1 = a0, a2 = a0, a3 = a0;
    #pragma unroll
    for (int k = 0; k < 32; k++) {
        float4 wv4 = *(const float4*)(wp + (size_t)k * stride);
        float h0 = shh[k], h1 = shh[64 + k], h2 = shh[128 + k], h3 = shh[192 + k];
        a0.x = fmaf(h0, wv4.x, a0.x); a0.y = fmaf(h0, wv4.y, a0.y);
        a0.z = fmaf(h0, wv4.z, a0.z); a0.w = fmaf(h0, wv4.w, a0.w);
        a1.x = fmaf(h1, wv4.x, a1.x); a1.y = fmaf(h1, wv4.y, a1.y);
        a1.z = fmaf(h1, wv4.z, a1.z); a1.w = fmaf(h1, wv4.w, a1.w);
        a2.x = fmaf(h2, wv4.x, a2.x); a2.y = fmaf(h2, wv4.y, a2.y);
        a2.z = fmaf(h2, wv4.z, a2.z); a2.w = fmaf(h2, wv4.w, a2.w);
        a3.x = fmaf(h3, wv4.x, a3.x); a3.y = fmaf(h3, wv4.y, a3.y);
        a3.z = fmaf(h3, wv4.z, a3.z); a3.w = fmaf(h3, wv4.w, a3.w);
    }
    if (half == 1) {
        float4* cb = (float4*)(comb + t * 16);
        cb[0] = a0; cb[1] = a1; cb[2] = a2; cb[3] = a3;
    }
    __syncthreads();
    if (half == 0) {
        const float4* cb = (const float4*)(comb + t * 16);
        float4 b0 = cb[0], b1 = cb[1], b2 = cb[2], b3 = cb[3];
        a0.x += b0.x; a0.y += b0.y; a0.z += b0.z; a0.w += b0.w;
        a1.x += b1.x; a1.y += b1.y; a1.z += b1.z; a1.w += b1.w;
        a2.x += b2.x; a2.y += b2.y; a2.z += b2.z; a2.w += b2.w;
        a3.x += b3.x; a3.y += b3.y; a3.z += b3.z; a3.w += b3.w;
        int c = c0 + t * 4;
        atomicAdd(&g_qkv[c],     a0.x); atomicAdd(&g_qkv[c + 1],     a0.y);
        atomicAdd(&g_qkv[c + 2], a0.z); atomicAdd(&g_qkv[c + 3],     a0.w);
        atomicAdd(&g_qkv[NTOT + c],     a1.x); atomicAdd(&g_qkv[NTOT + c + 1], a1.y);
        atomicAdd(&g_qkv[NTOT + c + 2], a1.z); atomicAdd(&g_qkv[NTOT + c + 3], a1.w);
        atomicAdd(&g_qkv[2*NTOT + c],     a2.x); atomicAdd(&g_qkv[2*NTOT + c + 1], a2.y);
        atomicAdd(&g_qkv[2*NTOT + c + 2], a2.z); atomicAdd(&g_qkv[2*NTOT + c + 3], a2.w);
        atomicAdd(&g_qkv[3*NTOT + c],     a3.x); atomicAdd(&g_qkv[3*NTOT + c + 1], a3.y);
        atomicAdd(&g_qkv[3*NTOT + c + 2], a3.z); atomicAdd(&g_qkv[3*NTOT + c + 3], a3.w);
    }
}

// ------------- Kernel 2: RoPE + accumulator reset -------------
__global__ void qkv_reduce(const float* __restrict__ cosp, const float* __restrict__ sinp) {
    int idx = blockIdx.x * blockDim.x + threadIdx.x;
    if (idx >= 4 * 3584) return;
    int b = idx / 3584, r = idx % 3584;
    float* gq = g_qkv + b * NTOT;
    if (r < 2560) {
        int head = r >> 6, d = r & 63;
        int col1 = head * 128 + d, col2 = col1 + 64;
        float s1 = gq[col1], s2 = gq[col2];
        gq[col1] = 0.f; gq[col2] = 0.f;
        float c1 = cosp[b * D_ + d],      sn1 = sinp[b * D_ + d];
        float c2 = cosp[b * D_ + d + 64], sn2 = sinp[b * D_ + d + 64];
        float r1 = s1 * c1 - s2 * sn1;
        float r2 = s2 * c2 + s1 * sn2;
        if (head < 32) {
            g_q[(b * HQ_ + head) * D_ + d]      = r1;
            g_q[(b * HQ_ + head) * D_ + d + 64] = r2;
        } else {
            int kh = head - 32;
            g_knew[(b * HKV_ + kh) * D_ + d]      = r1;
            g_knew[(b * HKV_ + kh) * D_ + d + 64] = r2;
        }
    } else {
        int lc = r - 2560;
        float s = gq[5120 + lc];
        gq[5120 + lc] = 0.f;
        g_vnew[b * HKV_ * D_ + lc] = s;
    }
}

// ------------- Kernel 3: scores (fast-path unroll 4 — the single change vs R11) -------------
__global__ void scores_kernel(const float* __restrict__ pk) {
    int bh = blockIdx.y;
    int b = bh >> 3, hkv = bh & 7;
    int tid = threadIdx.x, warp = tid >> 5, lane = tid & 31;
    __shared__ float qsh[512];
    const float* qsrc = g_q + (size_t)(b * HQ_ + hkv * 4) * D_;
    for (int i = tid; i < 512; i += 256) qsh[i] = qsrc[i];
    __syncthreads();
    float4 q0 = *(const float4*)(qsh +   0 + lane * 4);
    float4 q1 = *(const float4*)(qsh + 128 + lane * 4);
    float4 q2 = *(const float4*)(qsh + 256 + lane * 4);
    float4 q3 = *(const float4*)(qsh + 384 + lane * 4);
    int base = blockIdx.x * 256;
    float* srow = g_scores + (size_t)(b * HQ_ + hkv * 4) * SSTRIDE;
    const float* kbase = pk + ((size_t)bh << 20);
    const float* knrow = g_knew + bh * D_;
    int rr = ((lane >> 4) & 1) * 2 + ((lane >> 3) & 1);
    int hh = ((lane >> 2) & 1) * 2 + ((lane >> 1) & 1);
    int p0 = base + warp * 32;
    bool fast = (p0 + 31 < SPAST);
    if (fast) {
        #pragma unroll 4
        for (int j = 0; j < 32; j += 4) {
            int p = p0 + j;
            const float* rp = kbase + ((size_t)p << 7) + lane * 4;
            float4 k0v = *(const float4*)(rp);
            float4 k1v = *(const float4*)(rp + 128);
            float4 k2v = *(const float4*)(rp + 256);
            float4 k3v = *(const float4*)(rp + 384);
            float d00 = dot4(k0v, q0), d01 = dot4(k0v, q1), d02 = dot4(k0v, q2), d03 = dot4(k0v, q3);
            float d10 = dot4(k1v, q0), d11 = dot4(k1v, q1), d12 = dot4(k1v, q2), d13 = dot4(k1v, q3);
            float d20 = dot4(k2v, q0), d21 = dot4(k2v, q1), d22 = dot4(k2v, q2), d23 = dot4(k2v, q3);
            float d30 = dot4(k3v, q0), d31 = dot4(k3v, q1), d32 = dot4(k3v, q2), d33 = dot4(k3v, q3);
            float t00 = fold(d00, d20, 16, lane), t01 = fold(d01, d21, 16, lane);
            float t02 = fold(d02, d22, 16, lane), t03 = fold(d03, d23, 16, lane);
            float t10 = fold(d10, d30, 16, lane), t11 = fold(d11, d31, 16, lane);
            float t12 = fold(d12, d32, 16, lane), t13 = fold(d13, d33, 16, lane);
            float u0 = fold(t00, t10, 8, lane), u1 = fold(t01, t11, 8, lane);
            float u2 = fold(t02, t12, 8, lane), u3 = fold(t03, t13, 8, lane);
            float w0 = fold(u0, u2, 4, lane), w1 = fold(u1, u3, 4, lane);
            float x = fold(w0, w1, 2, lane);
            x += __shfl_xor_sync(0xFFFFFFFFu, x, 1);
            if ((lane & 1) == 0)
                srow[hh * SSTRIDE + p + rr] = x * SCALE;
        }
    } else {
        for (int j = 0; j < 32; j += 4) {
            int p = p0 + j;
            if (p >= KVLEN) break;
            const float* r0p = (p     < SPAST) ? kbase + ((size_t) p      << 7) : knrow;
            const float* r1p = (p + 1 < SPAST) ? kbase + ((size_t)(p + 1) << 7) : knrow;
            const float* r2p = (p + 2 < SPAST) ? kbase + ((size_t)(p + 2) << 7) : knrow;
            const float* r3p = (p + 3 < SPAST) ? kbase + ((size_t)(p + 3) << 7) : knrow;
            float4 k0v = *(const float4*)(r0p + lane * 4);
            float4 k1v = *(const float4*)(r1p + lane * 4);
            float4 k2v = *(const float4*)(r2p + lane * 4);
            float4 k3v = *(const float4*)(r3p + lane * 4);
            float d00 = dot4(k0v, q0), d01 = dot4(k0v, q1), d02 = dot4(k0v, q2), d03 = dot4(k0v, q3);
            float d10 = dot4(k1v, q0), d11 = dot4(k1v, q1), d12 = dot4(k1v, q2), d13 = dot4(k1v, q3);
            float d20 = dot4(k2v, q0), d21 = dot4(k2v, q1), d22 = dot4(k2v, q2), d23 = dot4(k2v, q3);
            float d30 = dot4(k3v, q0), d31 = dot4(k3v, q1), d32 = dot4(k3v, q2), d33 = dot4(k3v, q3);
            float t00 = fold(d00, d20, 16, lane), t01 = fold(d01, d21, 16, lane);
            float t02 = fold(d02, d22, 16, lane), t03 = fold(d03, d23, 16, lane);
            float t10 = fold(d10, d30, 16, lane), t11 = fold(d11, d31, 16, lane);
            float t12 = fold(d12, d32, 16, lane), t13 = fold(d13, d33, 16, lane);
            float u0 = fold(t00, t10, 8, lane), u1 = fold(t01, t11, 8, lane);
            float u2 = fold(t02, t12, 8, lane), u3 = fold(t03, t13, 8, lane);
            float w0 = fold(u0, u2, 4, lane), w1 = fold(u1, u3, 4, lane);
            float x = fold(w0, w1, 2, lane);
            x += __shfl_xor_sync(0xFFFFFFFFu, x, 1);
            if ((lane & 1) == 0 && p + rr < KVLEN)
                srow[hh * SSTRIDE + p + rr] = x * SCALE;
        }
    }
}

// ------------- Kernel 4: FUSED select (3-level radix, register keys) + softmax + V gather -------------
// (R11 version — fastest measured; do not warp-specialize)
#define KPT 8
template<int NB>
__device__ __forceinline__ void scan_pick_desc(const int* hist, int* warpsums,
                                               int* sh_bin, int* sh_kk, int tid) {
    int kk = *sh_kk;
    int nb = 1024 * NB;
    int b0 = nb - 1 - tid * NB;
    int c[NB]; int s = 0;
    #pragma unroll
    for (int q = 0; q < NB; q++) { c[q] = hist[b0 - q]; s += c[q]; }
    int v = s; int lane = tid & 31;
    #pragma unroll
    for (int o = 1; o < 32; o <<= 1) {
        int n = __shfl_up_sync(0xFFFFFFFFu, v, o);
        if (lane >= o) v += n;
    }
    if (lane == 31) warpsums[tid >> 5] = v;
    __syncthreads();
    if (tid == 0) {
        int a = 0;
        #pragma unroll
        for (int w = 0; w < 32; w++) { int t = warpsums[w]; warpsums[w] = a; a += t; }
    }
    __syncthreads();
    int excl = v - s + warpsums[tid >> 5];
    if (excl < kk && excl + s >= kk) {
        int acc = excl;
        #pragma unroll
        for (int q = 0; q < NB; q++) {
            if (acc < kk && acc + c[q] >= kk) { *sh_bin = b0 - q; *sh_kk = kk - acc; break; }
            acc += c[q];
        }
    }
    __syncthreads();
}
__device__ __forceinline__ void scan_pick_256(const int* hist, int* warpsums,
                                              int* sh_bin, int* sh_kk, int tid) {
    int kk = *sh_kk;
    int v = 0, s = 0;
    if (tid < 256) {
        s = hist[255 - tid];
        v = s;
        int lane = tid & 31;
        #pragma unroll
        for (int o = 1; o < 32; o <<= 1) {
            int n = __shfl_up_sync(0xFFFFFFFFu, v, o);
            if (lane >= o) v += n;
        }
        if (lane == 31) warpsums[tid >> 5] = v;
    }
    __syncthreads();
    if (tid == 0) {
        int a = 0;
        #pragma unroll
        for (int w = 0; w < 8; w++) { int t = warpsums[w]; warpsums[w] = a; a += t; }
    }
    __syncthreads();
    if (tid < 256) {
        v += warpsums[tid >> 5];
        int prev = v - s;
        if (v >= kk && prev < kk) { *sh_bin = 255 - tid; *sh_kk = kk - prev; }
    }
    __syncthreads();
}

__global__ __launch_bounds__(1024, 1)
void select_attnv_kernel(const float* __restrict__ pv, float* __restrict__ out) {
    __shared__ __align__(16) char s_buf[32768];
    __shared__ int warpsums[32];
    __shared__ int sh_bin, sh_kk, sh_wpos, sh_eq;
    __shared__ int selsh[TOKB];
    __shared__ float sc[NKEEP];
    __shared__ int   idxsh[NKEEP];
    __shared__ float red[32];
    __shared__ float M_sh, Z_sh;
    int* hist = (int*)s_buf;
    float* outsh = (float*)s_buf;

    int bh = blockIdx.x, tid = threadIdx.x;
    int b = bh >> 5, hq = bh & 31, hkv = hq >> 2;
    int warp = tid >> 5, lane = tid & 31;
    if (tid < 128) out[bh * 128 + tid] = 0.f;
    const float* srow = g_scores + (size_t)bh * SSTRIDE;

    hist[tid] = 0; hist[tid + 1024] = 0;
    if (tid == 0) { sh_kk = TOKB; sh_wpos = 0; sh_eq = 0; }
    __syncthreads();
    unsigned key[KPT];
    int ibase = tid * KPT;
    if (ibase + KPT - 1 < NCAND) {
        float4 f0 = *(const float4*)(srow + INITB + ibase);
        float4 f1 = *(const float4*)(srow + INITB + ibase + 4);
        key[0] = xform(__float_as_uint(f0.x)); key[1] = xform(__float_as_uint(f0.y));
        key[2] = xform(__float_as_uint(f0.z)); key[3] = xform(__float_as_uint(f0.w));
        key[4] = xform(__float_as_uint(f1.x)); key[5] = xform(__float_as_uint(f1.y));
        key[6] = xform(__float_as_uint(f1.z)); key[7] = xform(__float_as_uint(f1.w));
        #pragma unroll
        for (int j = 0; j < KPT; j++) atomicAdd(&hist[key[j] >> 21], 1);
    } else {
        #pragma unroll
        for (int j = 0; j < KPT; j++) {
            int i = ibase + j;
            unsigned u = 0;
            if (i < NCAND) {
                u = xform(__float_as_uint(srow[INITB + i]));
                atomicAdd(&hist[u >> 21], 1);
            }
            key[j] = u;
        }
    }
    __syncthreads();
    scan_pick_desc<2>(hist, warpsums, &sh_bin, &sh_kk, tid);
    unsigned B1 = (unsigned)sh_bin;
    #pragma unroll
    for (int q = 0; q < 8; q++) hist[tid + q * 1024] = 0;
    __syncthreads();
    #pragma unroll
    for (int j = 0; j < KPT; j++) {
        int i = ibase + j;
        if (i < NCAND) {
            unsigned t = key[j] >> 21;
            if (t > B1) selsh[atomicAdd(&sh_wpos, 1)] = INITB + i;
            else if (t == B1) atomicAdd(&hist[(key[j] >> 8) & 0x1FFF], 1);
        }
    }
    __syncthreads();
    scan_pick_desc<8>(hist, warpsums, &sh_bin, &sh_kk, tid);
    unsigned B2 = (unsigned)sh_bin;
    unsigned P24 = (B1 << 13) | B2;
    if (tid < 256) hist[tid] = 0;
    __syncthreads();
    #pragma unroll
    for (int j = 0; j < KPT; j++) {
        int i = ibase + j;
        if (i < NCAND && (key[j] >> 21) == B1) {
            unsigned t = (key[j] >> 8) & 0x1FFF;
            if (t > B2) selsh[atomicAdd(&sh_wpos, 1)] = INITB + i;
            else if (t == B2) atomicAdd(&hist[key[j] & 255], 1);
        }
    }
    __syncthreads();
    scan_pick_256(hist, warpsums, &sh_bin, &sh_kk, tid);
    unsigned tau = (P24 << 8) | (unsigned)sh_bin;
    int needeq = sh_kk;
    #pragma unroll
    for (int j = 0; j < KPT; j++) {
        int i = ibase + j;
        if (i < NCAND && (key[j] >> 8) == P24) {
            if (key[j] > tau) selsh[atomicAdd(&sh_wpos, 1)] = INITB + i;
            else if (key[j] == tau) {
                if (atomicAdd(&sh_eq, 1) < needeq)
                    selsh[atomicAdd(&sh_wpos, 1)] = INITB + i;
            }
        }
    }
    __syncthreads();

    // ---- attnv phase ----
    if (tid < NKEEP) {
        int i = tid, p;
        if (i < INITB) p = i;
        else if (i < INITB + TOKB) p = selsh[i - INITB];
        else p = (KVLEN - RECB) + (i - INITB - TOKB);
        idxsh[i] = p;
        sc[i] = srow[p];
    }
    __syncthreads();
    float m = (tid < NKEEP) ? sc[tid] : -INFINITY;
    m = warpmax(m);
    if (lane == 0) red[warp] = m;
    __syncthreads();
    if (tid == 0) {
        float mm = red[0];
        #pragma unroll
        for (int w = 1; w < 32; w++) mm = fmaxf(mm, red[w]);
        M_sh = mm;
    }
    __syncthreads();
    float M = M_sh;
    float z = 0.f;
    if (tid < NKEEP) {
        float e = __expf(sc[tid] - M);
        sc[tid] = e;
        z = e;
    }
    z = warpsum(z);
    if (lane == 0) red[warp] = z;
    __syncthreads();
    if (tid == 0) {
        float zz = 0.f;
        #pragma unroll
        for (int w = 0; w < 32; w++) zz += red[w];
        Z_sh = zz;
    }
    __syncthreads();
    float inv = 1.0f / Z_sh;
    float4 acc = make_float4(0.f, 0.f, 0.f, 0.f);
    const float* vbase = pv + ((size_t)(b * HKV_ + hkv) << 20);
    const float* vnrow = g_vnew + (b * HKV_ + hkv) * D_;
    for (int i = warp; i < NKEEP; i += 128) {
        float ww[4];
        const float* vp[4];
        #pragma unroll
        for (int u = 0; u < 4; u++) {
            int ii = i + u * 32;
            bool vld = ii < NKEEP;
            int p = vld ? idxsh[ii] : 0;
            ww[u] = vld ? sc[ii] * inv : 0.f;
            vp[u] = (p < SPAST) ? (vbase + ((size_t)p << 7)) : vnrow;
        }
        float4 v0 = *(const float4*)(vp[0] + lane * 4);
        float4 v1 = *(const float4*)(vp[1] + lane * 4);
        float4 v2 = *(const float4*)(vp[2] + lane * 4);
        float4 v3 = *(const float4*)(vp[3] + lane * 4);
        acc.x = fmaf(ww[0], v0.x, acc.x); acc.y = fmaf(ww[0], v0.y, acc.y);
        acc.z = fmaf(ww[0], v0.z, acc.z); acc.w = fmaf(ww[0], v0.w, acc.w);
        acc.x = fmaf(ww[1], v1.x, acc.x); acc.y = fmaf(ww[1], v1.y, acc.y);
        acc.z = fmaf(ww[1], v1.z, acc.z); acc.w = fmaf(ww[1], v1.w, acc.w);
        acc.x = fmaf(ww[2], v2.x, acc.x); acc.y = fmaf(ww[2], v2.y, acc.y);
        acc.z = fmaf(ww[2], v2.z, acc.z); acc.w = fmaf(ww[2], v2.w, acc.w);
        acc.x = fmaf(ww[3], v3.x, acc.x); acc.y = fmaf(ww[3], v3.y, acc.y);
        acc.z = fmaf(ww[3], v3.z, acc.z); acc.w = fmaf(ww[3], v3.w, acc.w);
    }
    float* os = outsh + warp * 128 + lane * 4;
    os[0] = acc.x; os[1] = acc.y; os[2] = acc.z; os[3] = acc.w;
    __syncthreads();
    if (tid < 128) {
        float s = 0.f;
        #pragma unroll
        for (int w = 0; w < 32; w++) s += outsh[w * 128 + tid];
        g_attn[bh * D_ + tid] = s;
    }
}

// ------------- Kernel 5: output projection GEMV (2-way intra-block k-split, FULL unroll) -------------
__global__ __launch_bounds__(256)
void out_gemv(const float* __restrict__ wo, float* __restrict__ out) {
    __shared__ float sh[256];
    __shared__ float comb[2048];
    int tid = threadIdx.x;
    int t = tid & 127, half = tid >> 7;
    int k0 = blockIdx.y * 64;
    {
        int b = tid >> 6, k = tid & 63;
        sh[tid] = g_attn[b * HID + k0 + k];
    }
    __syncthreads();
    int col = blockIdx.x * 512 + t * 4;
    const float* wp = wo + (size_t)(k0 + half * 32) * HID + col;
    const float* shh = sh + half * 32;
    float4 a0 = make_float4(0,0,0,0), a1 = a0, a2 = a0, a3 = a0;
    #pragma unroll
    for (int k = 0; k < 32; k++) {
        float4 wv4 = *(const float4*)(wp + (size_t)k * HID);
        float h0 = shh[k], h1 = shh[64 + k], h2 = shh[128 + k], h3 = shh[192 + k];
        a0.x = fmaf(h0, wv4.x, a0.x); a0.y = fmaf(h0, wv4.y, a0.y);
        a0.z = fmaf(h0, wv4.z, a0.z); a0.w = fmaf(h0, wv4.w, a0.w);
        a1.x = fmaf(h1, wv4.x, a1.x); a1.y = fmaf(h1, wv4.y, a1.y);
        a1.z = fmaf(h1, wv4.z, a1.z); a1.w = fmaf(h1, wv4.w, a1.w);
        a2.x = fmaf(h2, wv4.x, a2.x); a2.y = fmaf(h2, wv4.y, a2.y);
        a2.z = fmaf(h2, wv4.z, a2.z); a2.w = fmaf(h2, wv4.w, a2.w);
        a3.x = fmaf(h3, wv4.x, a3.x); a3.y = fmaf(h3, wv4.y, a3.y);
        a3.z = fmaf(h3, wv4.z, a3.z); a3.w = fmaf(h3, wv4.w, a3.w);
    }
    if (half == 1) {
        float4* cb = (float4*)(comb + t * 16);
        cb[0] = a0; cb[1] = a1; cb[2] = a2; cb[3] = a3;
    }
    __syncthreads();
    if (half == 0) {
        const float4* cb = (const float4*)(comb + t * 16);
        float4 b0 = cb[0], b1 = cb[1], b2 = cb[2], b3 = cb[3];
        a0.x += b0.x; a0.y += b0.y; a0.z += b0.z; a0.w += b0.w;
        a1.x += b1.x; a1.y += b1.y; a1.z += b1.z; a1.w += b1.w;
        a2.x += b2.x; a2.y += b2.y; a2.z += b2.z; a2.w += b2.w;
        a3.x += b3.x; a3.y += b3.y; a3.z += b3.z; a3.w += b3.w;
        atomicAdd(&out[col],     a0.x); atomicAdd(&out[col + 1],     a0.y);
        atomicAdd(&out[col + 2], a0.z); atomicAdd(&out[col + 3],     a0.w);
        atomicAdd(&out[HID + col],     a1.x); atomicAdd(&out[HID + col + 1], a1.y);
        atomicAdd(&out[HID + col + 2], a1.z); atomicAdd(&out[HID + col + 3], a1.w);
        atomicAdd(&out[2*HID + col],     a2.x); atomicAdd(&out[2*HID + col + 1], a2.y);
        atomicAdd(&out[2*HID + col + 2], a2.z); atomicAdd(&out[2*HID + col + 3], a2.w);
        atomicAdd(&out[3*HID + col],     a3.x); atomicAdd(&out[3*HID + col + 1], a3.y);
        atomicAdd(&out[3*HID + col + 2], a3.z); atomicAdd(&out[3*HID + col + 3], a3.w);
    }
}

// ------------- launch -------------
extern "C" void kernel_launch(void* const* d_in, const int* in_sizes, int n_in,
                              void* d_out, int out_size) {
    const float* h    = (const float*)d_in[0];
    const float* cosp = (const float*)d_in[1];
    const float* sinp = (const float*)d_in[2];
    const float* pk   = (const float*)d_in[3];
    const float* pv   = (const float*)d_in[4];
    const float* wq   = (const float*)d_in[5];
    const float* wk   = (const float*)d_in[6];
    const float* wv   = (const float*)d_in[7];
    const float* wo   = (const float*)d_in[8];
    float* out = (float*)d_out;

    qkv_gemv<<<dim3(12, NSPLIT), 256>>>(h, wq, wk, wv);
    qkv_reduce<<<(4 * 3584 + 255) / 256, 256>>>(cosp, sinp);
    scores_kernel<<<dim3(33, 32), 256>>>(pk);
    select_attnv_kernel<<<128, 1024>>>(pv, out);
    out_gemv<<<dim3(8, NSPLIT), 256>>>(wo, out);
}

// round 15
// speedup vs baseline: 1.1054x; 1.0764x over previous
#include <cuda_runtime.h>
#include <math.h>

// Problem constants
#define B_    4
#define HQ_   32
#define HKV_  8
#define D_    128
#define SPAST 8192
#define KVLEN 8193
#define HID   4096
#define NTOT  6144
#define TOKB  256
#define INITB 4
#define RECB  256
#define NKEEP (INITB + TOKB + RECB)   // 516
#define NCAND 7933                    // positions [4, 7936]
#define SSTRIDE 8208
#define SCALE 0.08838834764831845f
#define NSPLIT 64

// ------------- scratch -------------
__device__ float g_qkv   [4 * NTOT];   // atomically accumulated; reset by out_gemv each replay
__device__ float g_scores[B_ * HQ_ * SSTRIDE];
__device__ float g_attn  [B_ * HQ_ * D_];

// ------------- helpers -------------
__device__ __forceinline__ float warpsum(float v) {
    #pragma unroll
    for (int o = 16; o > 0; o >>= 1) v += __shfl_xor_sync(0xFFFFFFFFu, v, o);
    return v;
}
__device__ __forceinline__ float warpmax(float v) {
    #pragma unroll
    for (int o = 16; o > 0; o >>= 1) v = fmaxf(v, __shfl_xor_sync(0xFFFFFFFFu, v, o));
    return v;
}
__device__ __forceinline__ float dot4(float4 a, float4 b) {
    return a.x * b.x + a.y * b.y + a.z * b.z + a.w * b.w;
}
__device__ __forceinline__ float fold(float lo, float hi, int o, int lane) {
    float mine  = (lane & o) ? hi : lo;
    float other = (lane & o) ? lo : hi;
    return mine + __shfl_xor_sync(0xFFFFFFFFu, other, o);
}
__device__ __forceinline__ unsigned xform(unsigned u) {
    return (u & 0x80000000u) ? ~u : (u | 0x80000000u);
}

// ------------- Kernel 1: QKV GEMV (split-K=64, 2-way intra-block k-split, FULL unroll) -------------
__global__ __launch_bounds__(256)
void qkv_gemv(const float* __restrict__ h, const float* __restrict__ wq,
              const float* __restrict__ wk, const float* __restrict__ wv) {
    __shared__ float sh[256];
    __shared__ float comb[2048];
    int tid = threadIdx.x;
    int t = tid & 127, half = tid >> 7;
    int k0 = blockIdx.y * 64;
    {
        int b = tid >> 6, k = tid & 63;
        sh[tid] = h[b * HID + k0 + k];
    }
    __syncthreads();
    int c0 = blockIdx.x * 512;
    const float* w; int stride, col;
    if (c0 < 4096)      { w = wq; stride = 4096; col = c0; }
    else if (c0 < 5120) { w = wk; stride = 1024; col = c0 - 4096; }
    else                { w = wv; stride = 1024; col = c0 - 5120; }
    const float* wp = w + (size_t)(k0 + half * 32) * stride + col + t * 4;
    const float* shh = sh + half * 32;
    float4 a0 = make_float4(0,0,0,0), a1 = a0, a2 = a0, a3 = a0;
    #pragma unroll
    for (int k = 0; k < 32; k++) {
        float4 wv4 = *(const float4*)(wp + (size_t)k * stride);
        float h0 = shh[k], h1 = shh[64 + k], h2 = shh[128 + k], h3 = shh[192 + k];
        a0.x = fmaf(h0, wv4.x, a0.x); a0.y = fmaf(h0, wv4.y, a0.y);
        a0.z = fmaf(h0, wv4.z, a0.z); a0.w = fmaf(h0, wv4.w, a0.w);
        a1.x = fmaf(h1, wv4.x, a1.x); a1.y = fmaf(h1, wv4.y, a1.y);
        a1.z = fmaf(h1, wv4.z, a1.z); a1.w = fmaf(h1, wv4.w, a1.w);
        a2.x = fmaf(h2, wv4.x, a2.x); a2.y = fmaf(h2, wv4.y, a2.y);
        a2.z = fmaf(h2, wv4.z, a2.z); a2.w = fmaf(h2, wv4.w, a2.w);
        a3.x = fmaf(h3, wv4.x, a3.x); a3.y = fmaf(h3, wv4.y, a3.y);
        a3.z = fmaf(h3, wv4.z, a3.z); a3.w = fmaf(h3, wv4.w, a3.w);
    }
    if (half == 1) {
        float4* cb = (float4*)(comb + t * 16);
        cb[0] = a0; cb[1] = a1; cb[2] = a2; cb[3] = a3;
    }
    __syncthreads();
    if (half == 0) {
        const float4* cb = (const float4*)(comb + t * 16);
        float4 b0 = cb[0], b1 = cb[1], b2 = cb[2], b3 = cb[3];
        a0.x += b0.x; a0.y += b0.y; a0.z += b0.z; a0.w += b0.w;
        a1.x += b1.x; a1.y += b1.y; a1.z += b1.z; a1.w += b1.w;
        a2.x += b2.x; a2.y += b2.y; a2.z += b2.z; a2.w += b2.w;
        a3.x += b3.x; a3.y += b3.y; a3.z += b3.z; a3.w += b3.w;
        int c = c0 + t * 4;
        atomicAdd(&g_qkv[c],     a0.x); atomicAdd(&g_qkv[c + 1],     a0.y);
        atomicAdd(&g_qkv[c + 2], a0.z); atomicAdd(&g_qkv[c + 3],     a0.w);
        atomicAdd(&g_qkv[NTOT + c],     a1.x); atomicAdd(&g_qkv[NTOT + c + 1], a1.y);
        atomicAdd(&g_qkv[NTOT + c + 2], a1.z); atomicAdd(&g_qkv[NTOT + c + 3], a1.w);
        atomicAdd(&g_qkv[2*NTOT + c],     a2.x); atomicAdd(&g_qkv[2*NTOT + c + 1], a2.y);
        atomicAdd(&g_qkv[2*NTOT + c + 2], a2.z); atomicAdd(&g_qkv[2*NTOT + c + 3], a2.w);
        atomicAdd(&g_qkv[3*NTOT + c],     a3.x); atomicAdd(&g_qkv[3*NTOT + c + 1], a3.y);
        atomicAdd(&g_qkv[3*NTOT + c + 2], a3.z); atomicAdd(&g_qkv[3*NTOT + c + 3], a3.w);
    }
}

// ------------- Kernel 2: scores (in-block RoPE from g_qkv; qkv_reduce eliminated) -------------
__global__ void scores_kernel(const float* __restrict__ pk,
                              const float* __restrict__ cosp, const float* __restrict__ sinp) {
    int bh = blockIdx.y;
    int b = bh >> 3, hkv = bh & 7;
    int tid = threadIdx.x, warp = tid >> 5, lane = tid & 31;
    __shared__ float qsh[512];
    __shared__ float knsh[128];
    const float* gq = g_qkv + b * NTOT;
    // RoPE'd q for this block's 4 heads (redundant per bh; L2-hot)
    {
        int head = tid >> 6, d = tid & 63;      // tid < 256 covers 4 heads x 64 pairs
        int col = (hkv * 4 + head) * 128 + d;
        float s1 = gq[col], s2 = gq[col + 64];
        float c1 = cosp[b * D_ + d],      sn1 = sinp[b * D_ + d];
        float c2 = cosp[b * D_ + d + 64], sn2 = sinp[b * D_ + d + 64];
        qsh[head * 128 + d]      = s1 * c1 - s2 * sn1;
        qsh[head * 128 + d + 64] = s2 * c2 + s1 * sn2;
    }
    // tail block also needs RoPE'd k_new for this hkv
    if (blockIdx.x == 32 && tid < 64) {
        int d = tid;
        int col = 4096 + hkv * 128 + d;
        float s1 = gq[col], s2 = gq[col + 64];
        float c1 = cosp[b * D_ + d],      sn1 = sinp[b * D_ + d];
        float c2 = cosp[b * D_ + d + 64], sn2 = sinp[b * D_ + d + 64];
        knsh[d]      = s1 * c1 - s2 * sn1;
        knsh[d + 64] = s2 * c2 + s1 * sn2;
    }
    __syncthreads();
    float4 q0 = *(const float4*)(qsh +   0 + lane * 4);
    float4 q1 = *(const float4*)(qsh + 128 + lane * 4);
    float4 q2 = *(const float4*)(qsh + 256 + lane * 4);
    float4 q3 = *(const float4*)(qsh + 384 + lane * 4);
    int base = blockIdx.x * 256;
    float* srow = g_scores + (size_t)(b * HQ_ + hkv * 4) * SSTRIDE;
    const float* kbase = pk + ((size_t)bh << 20);
    const float* knrow = knsh;
    int rr = ((lane >> 4) & 1) * 2 + ((lane >> 3) & 1);
    int hh = ((lane >> 2) & 1) * 2 + ((lane >> 1) & 1);
    int p0 = base + warp * 32;
    bool fast = (p0 + 31 < SPAST);
    if (fast) {
        #pragma unroll 2
        for (int j = 0; j < 32; j += 4) {
            int p = p0 + j;
            const float* rp = kbase + ((size_t)p << 7) + lane * 4;
            float4 k0v = *(const float4*)(rp);
            float4 k1v = *(const float4*)(rp + 128);
            float4 k2v = *(const float4*)(rp + 256);
            float4 k3v = *(const float4*)(rp + 384);
            float d00 = dot4(k0v, q0), d01 = dot4(k0v, q1), d02 = dot4(k0v, q2), d03 = dot4(k0v, q3);
            float d10 = dot4(k1v, q0), d11 = dot4(k1v, q1), d12 = dot4(k1v, q2), d13 = dot4(k1v, q3);
            float d20 = dot4(k2v, q0), d21 = dot4(k2v, q1), d22 = dot4(k2v, q2), d23 = dot4(k2v, q3);
            float d30 = dot4(k3v, q0), d31 = dot4(k3v, q1), d32 = dot4(k3v, q2), d33 = dot4(k3v, q3);
            float t00 = fold(d00, d20, 16, lane), t01 = fold(d01, d21, 16, lane);
            float t02 = fold(d02, d22, 16, lane), t03 = fold(d03, d23, 16, lane);
            float t10 = fold(d10, d30, 16, lane), t11 = fold(d11, d31, 16, lane);
            float t12 = fold(d12, d32, 16, lane), t13 = fold(d13, d33, 16, lane);
            float u0 = fold(t00, t10, 8, lane), u1 = fold(t01, t11, 8, lane);
            float u2 = fold(t02, t12, 8, lane), u3 = fold(t03, t13, 8, lane);
            float w0 = fold(u0, u2, 4, lane), w1 = fold(u1, u3, 4, lane);
            float x = fold(w0, w1, 2, lane);
            x += __shfl_xor_sync(0xFFFFFFFFu, x, 1);
            if ((lane & 1) == 0)
                srow[hh * SSTRIDE + p + rr] = x * SCALE;
        }
    } else {
        for (int j = 0; j < 32; j += 4) {
            int p = p0 + j;
            if (p >= KVLEN) break;
            const float* r0p = (p     < SPAST) ? kbase + ((size_t) p      << 7) : knrow;
            const float* r1p = (p + 1 < SPAST) ? kbase + ((size_t)(p + 1) << 7) : knrow;
            const float* r2p = (p + 2 < SPAST) ? kbase + ((size_t)(p + 2) << 7) : knrow;
            const float* r3p = (p + 3 < SPAST) ? kbase + ((size_t)(p + 3) << 7) : knrow;
            float4 k0v = *(const float4*)(r0p + lane * 4);
            float4 k1v = *(const float4*)(r1p + lane * 4);
            float4 k2v = *(const float4*)(r2p + lane * 4);
            float4 k3v = *(const float4*)(r3p + lane * 4);
            float d00 = dot4(k0v, q0), d01 = dot4(k0v, q1), d02 = dot4(k0v, q2), d03 = dot4(k0v, q3);
            float d10 = dot4(k1v, q0), d11 = dot4(k1v, q1), d12 = dot4(k1v, q2), d13 = dot4(k1v, q3);
            float d20 = dot4(k2v, q0), d21 = dot4(k2v, q1), d22 = dot4(k2v, q2), d23 = dot4(k2v, q3);
            float d30 = dot4(k3v, q0), d31 = dot4(k3v, q1), d32 = dot4(k3v, q2), d33 = dot4(k3v, q3);
            float t00 = fold(d00, d20, 16, lane), t01 = fold(d01, d21, 16, lane);
            float t02 = fold(d02, d22, 16, lane), t03 = fold(d03, d23, 16, lane);
            float t10 = fold(d10, d30, 16, lane), t11 = fold(d11, d31, 16, lane);
            float t12 = fold(d12, d32, 16, lane), t13 = fold(d13, d33, 16, lane);
            float u0 = fold(t00, t10, 8, lane), u1 = fold(t01, t11, 8, lane);
            float u2 = fold(t02, t12, 8, lane), u3 = fold(t03, t13, 8, lane);
            float w0 = fold(u0, u2, 4, lane), w1 = fold(u1, u3, 4, lane);
            float x = fold(w0, w1, 2, lane);
            x += __shfl_xor_sync(0xFFFFFFFFu, x, 1);
            if ((lane & 1) == 0 && p + rr < KVLEN)
                srow[hh * SSTRIDE + p + rr] = x * SCALE;
        }
    }
}

// ------------- Kernel 3: FUSED select (3-level radix, register keys) + softmax + V gather -------------
// (R11 version — fastest measured; do not warp-specialize)
#define KPT 8
template<int NB>
__device__ __forceinline__ void scan_pick_desc(const int* hist, int* warpsums,
                                               int* sh_bin, int* sh_kk, int tid) {
    int kk = *sh_kk;
    int nb = 1024 * NB;
    int b0 = nb - 1 - tid * NB;
    int c[NB]; int s = 0;
    #pragma unroll
    for (int q = 0; q < NB; q++) { c[q] = hist[b0 - q]; s += c[q]; }
    int v = s; int lane = tid & 31;
    #pragma unroll
    for (int o = 1; o < 32; o <<= 1) {
        int n = __shfl_up_sync(0xFFFFFFFFu, v, o);
        if (lane >= o) v += n;
    }
    if (lane == 31) warpsums[tid >> 5] = v;
    __syncthreads();
    if (tid == 0) {
        int a = 0;
        #pragma unroll
        for (int w = 0; w < 32; w++) { int t = warpsums[w]; warpsums[w] = a; a += t; }
    }
    __syncthreads();
    int excl = v - s + warpsums[tid >> 5];
    if (excl < kk && excl + s >= kk) {
        int acc = excl;
        #pragma unroll
        for (int q = 0; q < NB; q++) {
            if (acc < kk && acc + c[q] >= kk) { *sh_bin = b0 - q; *sh_kk = kk - acc; break; }
            acc += c[q];
        }
    }
    __syncthreads();
}
__device__ __forceinline__ void scan_pick_256(const int* hist, int* warpsums,
                                              int* sh_bin, int* sh_kk, int tid) {
    int kk = *sh_kk;
    int v = 0, s = 0;
    if (tid < 256) {
        s = hist[255 - tid];
        v = s;
        int lane = tid & 31;
        #pragma unroll
        for (int o = 1; o < 32; o <<= 1) {
            int n = __shfl_up_sync(0xFFFFFFFFu, v, o);
            if (lane >= o) v += n;
        }
        if (lane == 31) warpsums[tid >> 5] = v;
    }
    __syncthreads();
    if (tid == 0) {
        int a = 0;
        #pragma unroll
        for (int w = 0; w < 8; w++) { int t = warpsums[w]; warpsums[w] = a; a += t; }
    }
    __syncthreads();
    if (tid < 256) {
        v += warpsums[tid >> 5];
        int prev = v - s;
        if (v >= kk && prev < kk) { *sh_bin = 255 - tid; *sh_kk = kk - prev; }
    }
    __syncthreads();
}

__global__ __launch_bounds__(1024, 1)
void select_attnv_kernel(const float* __restrict__ pv, float* __restrict__ out) {
    __shared__ __align__(16) char s_buf[32768];
    __shared__ int warpsums[32];
    __shared__ int sh_bin, sh_kk, sh_wpos, sh_eq;
    __shared__ int selsh[TOKB];
    __shared__ float sc[NKEEP];
    __shared__ int   idxsh[NKEEP];
    __shared__ float red[32];
    __shared__ float M_sh, Z_sh;
    int* hist = (int*)s_buf;
    float* outsh = (float*)s_buf;

    int bh = blockIdx.x, tid = threadIdx.x;
    int b = bh >> 5, hq = bh & 31, hkv = hq >> 2;
    int warp = tid >> 5, lane = tid & 31;
    if (tid < 128) out[bh * 128 + tid] = 0.f;
    const float* srow = g_scores + (size_t)bh * SSTRIDE;

    hist[tid] = 0; hist[tid + 1024] = 0;
    if (tid == 0) { sh_kk = TOKB; sh_wpos = 0; sh_eq = 0; }
    __syncthreads();
    unsigned key[KPT];
    int ibase = tid * KPT;
    if (ibase + KPT - 1 < NCAND) {
        float4 f0 = *(const float4*)(srow + INITB + ibase);
        float4 f1 = *(const float4*)(srow + INITB + ibase + 4);
        key[0] = xform(__float_as_uint(f0.x)); key[1] = xform(__float_as_uint(f0.y));
        key[2] = xform(__float_as_uint(f0.z)); key[3] = xform(__float_as_uint(f0.w));
        key[4] = xform(__float_as_uint(f1.x)); key[5] = xform(__float_as_uint(f1.y));
        key[6] = xform(__float_as_uint(f1.z)); key[7] = xform(__float_as_uint(f1.w));
        #pragma unroll
        for (int j = 0; j < KPT; j++) atomicAdd(&hist[key[j] >> 21], 1);
    } else {
        #pragma unroll
        for (int j = 0; j < KPT; j++) {
            int i = ibase + j;
            unsigned u = 0;
            if (i < NCAND) {
                u = xform(__float_as_uint(srow[INITB + i]));
                atomicAdd(&hist[u >> 21], 1);
            }
            key[j] = u;
        }
    }
    __syncthreads();
    scan_pick_desc<2>(hist, warpsums, &sh_bin, &sh_kk, tid);
    unsigned B1 = (unsigned)sh_bin;
    #pragma unroll
    for (int q = 0; q < 8; q++) hist[tid + q * 1024] = 0;
    __syncthreads();
    #pragma unroll
    for (int j = 0; j < KPT; j++) {
        int i = ibase + j;
        if (i < NCAND) {
            unsigned t = key[j] >> 21;
            if (t > B1) selsh[atomicAdd(&sh_wpos, 1)] = INITB + i;
            else if (t == B1) atomicAdd(&hist[(key[j] >> 8) & 0x1FFF], 1);
        }
    }
    __syncthreads();
    scan_pick_desc<8>(hist, warpsums, &sh_bin, &sh_kk, tid);
    unsigned B2 = (unsigned)sh_bin;
    unsigned P24 = (B1 << 13) | B2;
    if (tid < 256) hist[tid] = 0;
    __syncthreads();
    #pragma unroll
    for (int j = 0; j < KPT; j++) {
        int i = ibase + j;
        if (i < NCAND && (key[j] >> 21) == B1) {
            unsigned t = (key[j] >> 8) & 0x1FFF;
            if (t > B2) selsh[atomicAdd(&sh_wpos, 1)] = INITB + i;
            else if (t == B2) atomicAdd(&hist[key[j] & 255], 1);
        }
    }
    __syncthreads();
    scan_pick_256(hist, warpsums, &sh_bin, &sh_kk, tid);
    unsigned tau = (P24 << 8) | (unsigned)sh_bin;
    int needeq = sh_kk;
    #pragma unroll
    for (int j = 0; j < KPT; j++) {
        int i = ibase + j;
        if (i < NCAND && (key[j] >> 8) == P24) {
            if (key[j] > tau) selsh[atomicAdd(&sh_wpos, 1)] = INITB + i;
            else if (key[j] == tau) {
                if (atomicAdd(&sh_eq, 1) < needeq)
                    selsh[atomicAdd(&sh_wpos, 1)] = INITB + i;
            }
        }
    }
    __syncthreads();

    // ---- attnv phase ----
    if (tid < NKEEP) {
        int i = tid, p;
        if (i < INITB) p = i;
        else if (i < INITB + TOKB) p = selsh[i - INITB];
        else p = (KVLEN - RECB) + (i - INITB - TOKB);
        idxsh[i] = p;
        sc[i] = srow[p];
    }
    __syncthreads();
    float m = (tid < NKEEP) ? sc[tid] : -INFINITY;
    m = warpmax(m);
    if (lane == 0) red[warp] = m;
    __syncthreads();
    if (tid == 0) {
        float mm = red[0];
        #pragma unroll
        for (int w = 1; w < 32; w++) mm = fmaxf(mm, red[w]);
        M_sh = mm;
    }
    __syncthreads();
    float M = M_sh;
    float z = 0.f;
    if (tid < NKEEP) {
        float e = __expf(sc[tid] - M);
        sc[tid] = e;
        z = e;
    }
    z = warpsum(z);
    if (lane == 0) red[warp] = z;
    __syncthreads();
    if (tid == 0) {
        float zz = 0.f;
        #pragma unroll
        for (int w = 0; w < 32; w++) zz += red[w];
        Z_sh = zz;
    }
    __syncthreads();
    float inv = 1.0f / Z_sh;
    float4 acc = make_float4(0.f, 0.f, 0.f, 0.f);
    const float* vbase = pv + ((size_t)(b * HKV_ + hkv) << 20);
    const float* vnrow = g_qkv + b * NTOT + 5120 + hkv * 128;   // vnew = raw accumulated v (no RoPE)
    for (int i = warp; i < NKEEP; i += 128) {
        float ww[4];
        const float* vp[4];
        #pragma unroll
        for (int u = 0; u < 4; u++) {
            int ii = i + u * 32;
            bool vld = ii < NKEEP;
            int p = vld ? idxsh[ii] : 0;
            ww[u] = vld ? sc[ii] * inv : 0.f;
            vp[u] = (p < SPAST) ? (vbase + ((size_t)p << 7)) : vnrow;
        }
        float4 v0 = *(const float4*)(vp[0] + lane * 4);
        float4 v1 = *(const float4*)(vp[1] + lane * 4);
        float4 v2 = *(const float4*)(vp[2] + lane * 4);
        float4 v3 = *(const float4*)(vp[3] + lane * 4);
        acc.x = fmaf(ww[0], v0.x, acc.x); acc.y = fmaf(ww[0], v0.y, acc.y);
        acc.z = fmaf(ww[0], v0.z, acc.z); acc.w = fmaf(ww[0], v0.w, acc.w);
        acc.x = fmaf(ww[1], v1.x, acc.x); acc.y = fmaf(ww[1], v1.y, acc.y);
        acc.z = fmaf(ww[1], v1.z, acc.z); acc.w = fmaf(ww[1], v1.w, acc.w);
        acc.x = fmaf(ww[2], v2.x, acc.x); acc.y = fmaf(ww[2], v2.y, acc.y);
        acc.z = fmaf(ww[2], v2.z, acc.z); acc.w = fmaf(ww[2], v2.w, acc.w);
        acc.x = fmaf(ww[3], v3.x, acc.x); acc.y = fmaf(ww[3], v3.y, acc.y);
        acc.z = fmaf(ww[3], v3.z, acc.z); acc.w = fmaf(ww[3], v3.w, acc.w);
    }
    float* os = outsh + warp * 128 + lane * 4;
    os[0] = acc.x; os[1] = acc.y; os[2] = acc.z; os[3] = acc.w;
    __syncthreads();
    if (tid < 128) {
        float s = 0.f;
        #pragma unroll
        for (int w = 0; w < 32; w++) s += outsh[w * 128 + tid];
        g_attn[bh * D_ + tid] = s;
    }
}

// ------------- Kernel 4: output projection GEMV + g_qkv reset -------------
__global__ __launch_bounds__(256)
void out_gemv(const float* __restrict__ wo, float* __restrict__ out) {
    __shared__ float sh[256];
    __shared__ float comb[2048];
    int tid = threadIdx.x;
    int t = tid & 127, half = tid >> 7;
    int k0 = blockIdx.y * 64;
    // reset g_qkv for next replay: 512 blocks x 48 floats = 24576 exact
    {
        int rid = ((int)blockIdx.y * 8 + (int)blockIdx.x) * 48 + tid;
        if (tid < 48) g_qkv[rid] = 0.f;
    }
    {
        int b = tid >> 6, k = tid & 63;
        sh[tid] = g_attn[b * HID + k0 + k];
    }
    __syncthreads();
    int col = blockIdx.x * 512 + t * 4;
    const float* wp = wo + (size_t)(k0 + half * 32) * HID + col;
    const float* shh = sh + half * 32;
    float4 a0 = make_float4(0,0,0,0), a1 = a0, a2 = a0, a3 = a0;
    #pragma unroll
    for (int k = 0; k < 32; k++) {
        float4 wv4 = *(const float4*)(wp + (size_t)k * HID);
        float h0 = shh[k], h1 = shh[64 + k], h2 = shh[128 + k], h3 = shh[192 + k];
        a0.x = fmaf(h0, wv4.x, a0.x); a0.y = fmaf(h0, wv4.y, a0.y);
        a0.z = fmaf(h0, wv4.z, a0.z); a0.w = fmaf(h0, wv4.w, a0.w);
        a1.x = fmaf(h1, wv4.x, a1.x); a1.y = fmaf(h1, wv4.y, a1.y);
        a1.z = fmaf(h1, wv4.z, a1.z); a1.w = fmaf(h1, wv4.w, a1.w);
        a2.x = fmaf(h2, wv4.x, a2.x); a2.y = fmaf(h2, wv4.y, a2.y);
        a2.z = fmaf(h2, wv4.z, a2.z); a2.w = fmaf(h2, wv4.w, a2.w);
        a3.x = fmaf(h3, wv4.x, a3.x); a3.y = fmaf(h3, wv4.y, a3.y);
        a3.z = fmaf(h3, wv4.z, a3.z); a3.w = fmaf(h3, wv4.w, a3.w);
    }
    if (half == 1) {
        float4* cb = (float4*)(comb + t * 16);
        cb[0] = a0; cb[1] = a1; cb[2] = a2; cb[3] = a3;
    }
    __syncthreads();
    if (half == 0) {
        const float4* cb = (const float4*)(comb + t * 16);
        float4 b0 = cb[0], b1 = cb[1], b2 = cb[2], b3 = cb[3];
        a0.x += b0.x; a0.y += b0.y; a0.z += b0.z; a0.w += b0.w;
        a1.x += b1.x; a1.y += b1.y; a1.z += b1.z; a1.w += b1.w;
        a2.x += b2.x; a2.y += b2.y; a2.z += b2.z; a2.w += b2.w;
        a3.x += b3.x; a3.y += b3.y; a3.z += b3.z; a3.w += b3.w;
        atomicAdd(&out[col],     a0.x); atomicAdd(&out[col + 1],     a0.y);
        atomicAdd(&out[col + 2], a0.z); atomicAdd(&out[col + 3],     a0.w);
        atomicAdd(&out[HID + col],     a1.x); atomicAdd(&out[HID + col + 1], a1.y);
        atomicAdd(&out[HID + col + 2], a1.z); atomicAdd(&out[HID + col + 3], a1.w);
        atomicAdd(&out[2*HID + col],     a2.x); atomicAdd(&out[2*HID + col + 1], a2.y);
        atomicAdd(&out[2*HID + col + 2], a2.z); atomicAdd(&out[2*HID + col + 3], a2.w);
        atomicAdd(&out[3*HID + col],     a3.x); atomicAdd(&out[3*HID + col + 1], a3.y);
        atomicAdd(&out[3*HID + col + 2], a3.z); atomicAdd(&out[3*HID + col + 3], a3.w);
    }
}

// ------------- launch -------------
extern "C" void kernel_launch(void* const* d_in, const int* in_sizes, int n_in,
                              void* d_out, int out_size) {
    const float* h    = (const float*)d_in[0];
    const float* cosp = (const float*)d_in[1];
    const float* sinp = (const float*)d_in[2];
    const float* pk   = (const float*)d_in[3];
    const float* pv   = (const float*)d_in[4];
    const float* wq   = (const float*)d_in[5];
    const float* wk   = (const float*)d_in[6];
    const float* wv   = (const float*)d_in[7];
    const float* wo   = (const float*)d_in[8];
    float* out = (float*)d_out;

    qkv_gemv<<<dim3(12, NSPLIT), 256>>>(h, wq, wk, wv);
    scores_kernel<<<dim3(33, 32), 256>>>(pk, cosp, sinp);
    select_attnv_kernel<<<128, 1024>>>(pv, out);
    out_gemv<<<dim3(8, NSPLIT), 256>>>(wo, out);
}